// round 1
// baseline (speedup 1.0000x reference)
#include <cuda_runtime.h>
#include <cuda_bf16.h>
#include <cstddef>

// GridAttention factorized pipeline.
// Shapes: B=4, DM=256, W=H=256, GS=8 -> 4096 cells (bn), L=64 tokens, NH=8, dh=32.
//
// Math (exact rewrite of reference):
//  q[bn]      = mean over 64 patch pixels (per channel)
//  qp         = q @ Wq^T + bq
//  qk_h       = qp_h @ Wk_h          (256-vec per head)   qb_h = qp_h . bk_h
//  scores_h,l = (qk_h . kv_l + qb_h) / sqrt(32)
//  a          = softmax_l(scores)
//  wkv_h      = sum_l a_h,l * kv_l   (256-vec per head)
//  ctx_h      = wkv_h @ Wv_h^T + bv_h
//  out        = q + ctx @ Wo^T + bo

#define NCELLS 4096

// Scratch (static device globals; no allocations anywhere)
__device__ float g_Q[NCELLS * 256];        // pooled queries
__device__ float g_QK[NCELLS * 8 * 256];   // per-head query-key vectors
__device__ float g_QB[NCELLS * 8];         // per-head bias dot
__device__ float g_WKV[NCELLS * 8 * 256];  // attention-weighted kv per head

// ---------------------------------------------------------------------------
// K1: average-pool per grid cell.  grid (32 gi, 256 d, 4 b), 256 threads = h.
// ---------------------------------------------------------------------------
__global__ void k_pool(const float* __restrict__ x) {
    int gi = blockIdx.x, d = blockIdx.y, b = blockIdx.z;
    int t = threadIdx.x;  // h coordinate 0..255
    const float* p = x + ((size_t)(b * 256 + d) * 256 + (size_t)gi * 8) * 256 + t;
    float s = 0.f;
#pragma unroll
    for (int r = 0; r < 8; r++) s += p[r * 256];
    // reduce over 8 lanes (h within a cell)
    s += __shfl_down_sync(0xffffffffu, s, 4, 8);
    s += __shfl_down_sync(0xffffffffu, s, 2, 8);
    s += __shfl_down_sync(0xffffffffu, s, 1, 8);
    if ((t & 7) == 0) {
        int j = t >> 3;  // cell column 0..31
        g_Q[((b * 1024 + gi * 32 + j) * 256) + d] = s * (1.0f / 64.0f);
    }
}

// ---------------------------------------------------------------------------
// K2: qp = Q@Wq^T + bq ; qk_h = qp_h @ Wk_h ; qb_h = qp_h . bk_h
// 16 cells per block, 256 threads (thread = output column c).
// Weight tiles staged transposed in smem with +1 pad (conflict-free).
// ---------------------------------------------------------------------------
#define K2_CELLS 16
__global__ void k_qk(const float* __restrict__ Wq, const float* __restrict__ bq,
                     const float* __restrict__ Wk, const float* __restrict__ bk) {
    extern __shared__ float sm[];
    float* Qs  = sm;            // 16*256
    float* qps = sm + 4096;     // 16*256
    float* Ws  = sm + 8192;     // 32*257

    int t = threadIdx.x;
    int bn0 = blockIdx.x * K2_CELLS;

    for (int i = 0; i < K2_CELLS; i++) Qs[i * 256 + t] = g_Q[(bn0 + i) * 256 + t];

    float acc[K2_CELLS];
    float bqc = bq[t];
#pragma unroll
    for (int r = 0; r < K2_CELLS; r++) acc[r] = bqc;

    for (int k0 = 0; k0 < 256; k0 += 32) {
        __syncthreads();
        // Ws[k][c] = Wq[c][k0+k]  (coalesced read, stride-1-bank store)
#pragma unroll
        for (int i = 0; i < 32; i++) {
            int idx = i * 256 + t;
            int c = idx >> 5, k = idx & 31;
            Ws[k * 257 + c] = Wq[c * 256 + k0 + k];
        }
        __syncthreads();
#pragma unroll
        for (int k = 0; k < 32; k += 4) {
            float w0 = Ws[(k + 0) * 257 + t];
            float w1 = Ws[(k + 1) * 257 + t];
            float w2 = Ws[(k + 2) * 257 + t];
            float w3 = Ws[(k + 3) * 257 + t];
#pragma unroll
            for (int r = 0; r < K2_CELLS; r++) {
                float4 q = *(const float4*)&Qs[r * 256 + k0 + k];
                acc[r] = fmaf(q.x, w0, acc[r]);
                acc[r] = fmaf(q.y, w1, acc[r]);
                acc[r] = fmaf(q.z, w2, acc[r]);
                acc[r] = fmaf(q.w, w3, acc[r]);
            }
        }
    }
    __syncthreads();
    for (int r = 0; r < K2_CELLS; r++) qps[r * 256 + t] = acc[r];
    __syncthreads();

    // qb_h (zero when bk == 0, but computed generally)
    if (t < 128) {
        int r = t >> 3, h = t & 7;
        float s = 0.f;
#pragma unroll
        for (int j = 0; j < 32; j++) s += qps[r * 256 + h * 32 + j] * bk[h * 32 + j];
        g_QB[(bn0 + r) * 8 + h] = s;
    }

    // phase 2: qk_h[c] = sum_j qp[h*32+j] * Wk[h*32+j][c]
    for (int h = 0; h < 8; h++) {
        __syncthreads();
#pragma unroll
        for (int i = 0; i < 32; i++)
            Ws[i * 257 + t] = Wk[(h * 32 + i) * 256 + t];
        __syncthreads();
        float a2[K2_CELLS];
#pragma unroll
        for (int r = 0; r < K2_CELLS; r++) a2[r] = 0.f;
#pragma unroll
        for (int j = 0; j < 32; j += 4) {
            float w0 = Ws[(j + 0) * 257 + t];
            float w1 = Ws[(j + 1) * 257 + t];
            float w2 = Ws[(j + 2) * 257 + t];
            float w3 = Ws[(j + 3) * 257 + t];
#pragma unroll
            for (int r = 0; r < K2_CELLS; r++) {
                float4 q = *(const float4*)&qps[r * 256 + h * 32 + j];
                a2[r] = fmaf(q.x, w0, a2[r]);
                a2[r] = fmaf(q.y, w1, a2[r]);
                a2[r] = fmaf(q.z, w2, a2[r]);
                a2[r] = fmaf(q.w, w3, a2[r]);
            }
        }
        for (int r = 0; r < K2_CELLS; r++)
            g_QK[((bn0 + r) * 8 + h) * 256 + t] = a2[r];
    }
}

// ---------------------------------------------------------------------------
// K3: per-cell attention.  1 block per cell, 256 threads.
// kvs layout [d][l] with row pad 65 -> conflict-free for all 3 phases.
// ---------------------------------------------------------------------------
__global__ void k_attn(const float* __restrict__ x) {
    extern __shared__ float sm[];
    float* kvs  = sm;            // 256*65 = 16640
    float* qks  = sm + 16640;    // 8*256  = 2048
    float* psum = sm + 18688;    // 4*8*64 = 2048
    float* as_  = sm + 20736;    // 8*64   = 512
    float* qbs  = sm + 21248;    // 8

    int t = threadIdx.x;
    int bn = blockIdx.x;
    int b = bn >> 10, cell = bn & 1023, gi = cell >> 5, gj = cell & 31;

    const float* xb = x + (size_t)b * 16777216 + (size_t)gi * 2048 + (size_t)gj * 8;

    // load 64x256 patch: float4 over h (coalesced 32B sectors), store [d][l]
#pragma unroll
    for (int i = 0; i < 16; i++) {
        int idx = i * 256 + t;
        int d = idx >> 4, r = idx & 15;
        int sw = r >> 1, part = r & 1;
        float4 v = *(const float4*)(xb + (size_t)d * 65536 + sw * 256 + part * 4);
        int l = sw * 8 + part * 4;
        kvs[d * 65 + l + 0] = v.x;
        kvs[d * 65 + l + 1] = v.y;
        kvs[d * 65 + l + 2] = v.z;
        kvs[d * 65 + l + 3] = v.w;
    }
#pragma unroll
    for (int i = 0; i < 8; i++) qks[i * 256 + t] = g_QK[bn * 2048 + i * 256 + t];
    if (t < 8) qbs[t] = g_QB[bn * 8 + t];
    __syncthreads();

    // scores partials: thread (dq, l), accumulate all 8 heads over 64 d's
    {
        int l = t & 63, dq = t >> 6;
        float acc[8];
#pragma unroll
        for (int h = 0; h < 8; h++) acc[h] = 0.f;
        int dbase = dq * 64;
#pragma unroll 4
        for (int d = dbase; d < dbase + 64; d++) {
            float kv = kvs[d * 65 + l];
#pragma unroll
            for (int h = 0; h < 8; h++) acc[h] = fmaf(kv, qks[h * 256 + d], acc[h]);
        }
#pragma unroll
        for (int h = 0; h < 8; h++) psum[(dq * 8 + h) * 64 + l] = acc[h];
    }
    __syncthreads();

    // softmax: warp h handles head h (lanes cover l, l+32)
    {
        int wid = t >> 5, lane = t & 31;
        if (wid < 8) {
            int h = wid;
            float s1 = qbs[h], s2 = qbs[h];
#pragma unroll
            for (int dq = 0; dq < 4; dq++) {
                s1 += psum[(dq * 8 + h) * 64 + lane];
                s2 += psum[(dq * 8 + h) * 64 + lane + 32];
            }
            const float sc = 0.17677669529663687f;  // 1/sqrt(32)
            s1 *= sc; s2 *= sc;
            float m = fmaxf(s1, s2);
#pragma unroll
            for (int o = 16; o > 0; o >>= 1) m = fmaxf(m, __shfl_xor_sync(0xffffffffu, m, o));
            float e1 = __expf(s1 - m), e2 = __expf(s2 - m);
            float sum = e1 + e2;
#pragma unroll
            for (int o = 16; o > 0; o >>= 1) sum += __shfl_xor_sync(0xffffffffu, sum, o);
            float inv = 1.f / sum;
            as_[h * 64 + lane]      = e1 * inv;
            as_[h * 64 + lane + 32] = e2 * inv;
        }
    }
    __syncthreads();

    // wkv: thread = d, all 8 heads
    {
        int d = t;
        float acc[8];
#pragma unroll
        for (int h = 0; h < 8; h++) acc[h] = 0.f;
#pragma unroll 4
        for (int l = 0; l < 64; l++) {
            float kv = kvs[d * 65 + l];
#pragma unroll
            for (int h = 0; h < 8; h++) acc[h] = fmaf(kv, as_[h * 64 + l], acc[h]);
        }
#pragma unroll
        for (int h = 0; h < 8; h++) g_WKV[bn * 2048 + h * 256 + d] = acc[h];
    }
}

// ---------------------------------------------------------------------------
// K4: ctx = wkv @ Wv_h^T + bv ; out = q + ctx @ Wo^T + bo
// 8 cells per block, 256 threads.
// ---------------------------------------------------------------------------
#define K4_CELLS 8
__global__ void k_out(const float* __restrict__ Wv, const float* __restrict__ bv,
                      const float* __restrict__ Wo, const float* __restrict__ bo,
                      float* __restrict__ out) {
    extern __shared__ float sm[];
    float* wkvs = sm;            // 8*2048 = 16384
    float* ctxs = sm + 16384;    // 8*256  = 2048
    float* Ws   = sm + 18432;    // 32*257

    int t = threadIdx.x;
    int bn0 = blockIdx.x * K4_CELLS;

    for (int i = 0; i < 64; i++)
        wkvs[i * 256 + t] = g_WKV[bn0 * 2048 + i * 256 + t];

    int h = t >> 5;  // head of output index m = t
    float acc[K4_CELLS];
    float bvm = bv[t];
#pragma unroll
    for (int r = 0; r < K4_CELLS; r++) acc[r] = bvm;

    for (int d0 = 0; d0 < 256; d0 += 32) {
        __syncthreads();
#pragma unroll
        for (int i = 0; i < 32; i++) {
            int idx = i * 256 + t;
            int m = idx >> 5, k = idx & 31;
            Ws[k * 257 + m] = Wv[m * 256 + d0 + k];
        }
        __syncthreads();
#pragma unroll
        for (int k = 0; k < 32; k += 4) {
            float w0 = Ws[(k + 0) * 257 + t];
            float w1 = Ws[(k + 1) * 257 + t];
            float w2 = Ws[(k + 2) * 257 + t];
            float w3 = Ws[(k + 3) * 257 + t];
#pragma unroll
            for (int r = 0; r < K4_CELLS; r++) {
                float4 v = *(const float4*)&wkvs[r * 2048 + h * 256 + d0 + k];
                acc[r] = fmaf(v.x, w0, acc[r]);
                acc[r] = fmaf(v.y, w1, acc[r]);
                acc[r] = fmaf(v.z, w2, acc[r]);
                acc[r] = fmaf(v.w, w3, acc[r]);
            }
        }
    }
    __syncthreads();
    for (int r = 0; r < K4_CELLS; r++) ctxs[r * 256 + t] = acc[r];

    float acc2[K4_CELLS];
    float boc = bo[t];
#pragma unroll
    for (int r = 0; r < K4_CELLS; r++) acc2[r] = boc;

    for (int m0 = 0; m0 < 256; m0 += 32) {
        __syncthreads();
#pragma unroll
        for (int i = 0; i < 32; i++) {
            int idx = i * 256 + t;
            int c = idx >> 5, k = idx & 31;
            Ws[k * 257 + c] = Wo[c * 256 + m0 + k];
        }
        __syncthreads();
#pragma unroll
        for (int k = 0; k < 32; k += 4) {
            float w0 = Ws[(k + 0) * 257 + t];
            float w1 = Ws[(k + 1) * 257 + t];
            float w2 = Ws[(k + 2) * 257 + t];
            float w3 = Ws[(k + 3) * 257 + t];
#pragma unroll
            for (int r = 0; r < K4_CELLS; r++) {
                float4 c4 = *(const float4*)&ctxs[r * 256 + m0 + k];
                acc2[r] = fmaf(c4.x, w0, acc2[r]);
                acc2[r] = fmaf(c4.y, w1, acc2[r]);
                acc2[r] = fmaf(c4.z, w2, acc2[r]);
                acc2[r] = fmaf(c4.w, w3, acc2[r]);
            }
        }
    }
    for (int r = 0; r < K4_CELLS; r++)
        out[(bn0 + r) * 256 + t] = acc2[r] + g_Q[(bn0 + r) * 256 + t];
}

// ---------------------------------------------------------------------------
extern "C" void kernel_launch(void* const* d_in, const int* in_sizes, int n_in,
                              void* d_out, int out_size) {
    const float* x  = (const float*)d_in[0];
    const float* Wq = (const float*)d_in[1];
    const float* bq = (const float*)d_in[2];
    const float* Wk = (const float*)d_in[3];
    const float* bk = (const float*)d_in[4];
    const float* Wv = (const float*)d_in[5];
    const float* bv = (const float*)d_in[6];
    const float* Wo = (const float*)d_in[7];
    const float* bo = (const float*)d_in[8];
    float* out = (float*)d_out;

    const int smem_k2 = (16416) * 4;   // 65,664 B
    const int smem_k3 = (21256) * 4;   // 85,024 B
    const int smem_k4 = (26656) * 4;   // 106,624 B
    cudaFuncSetAttribute(k_qk,   cudaFuncAttributeMaxDynamicSharedMemorySize, smem_k2);
    cudaFuncSetAttribute(k_attn, cudaFuncAttributeMaxDynamicSharedMemorySize, smem_k3);
    cudaFuncSetAttribute(k_out,  cudaFuncAttributeMaxDynamicSharedMemorySize, smem_k4);

    k_pool<<<dim3(32, 256, 4), 256>>>(x);
    k_qk<<<NCELLS / K2_CELLS, 256, smem_k2>>>(Wq, bq, Wk, bk);
    k_attn<<<NCELLS, 256, smem_k3>>>(x);
    k_out<<<NCELLS / K4_CELLS, 256, smem_k4>>>(Wv, bv, Wo, bo, out);
}

// round 5
// speedup vs baseline: 1.0958x; 1.0958x over previous
#include <cuda_runtime.h>
#include <cuda_bf16.h>
#include <cstddef>

// GridAttention factorized pipeline (round-2 design; resubmit after broker timeouts).
// Shapes: B=4, DM=256, W=H=256, GS=8 -> 4096 cells, L=64 tokens, NH=8, dh=32.
//
//  q[bn]      = mean over 64 patch pixels (per channel)        (k_pool)
//  qp         = q @ Wq^T + bq                                  (k2a)
//  qb_h       = qp_h . bk_h                                    (k_qb)
//  qk_h       = qp_h @ Wk_h                                    (k2b)
//  scores_h,l = (qk_h . kv_l + qb_h) / sqrt(32); softmax; wkv  (k3)
//  ctx_h      = wkv_h @ Wv_h^T + bv_h                          (k4a)
//  out        = q + ctx @ Wo^T + bo                            (k4b)

#define NCELLS 4096

__device__ float g_Q[NCELLS * 256];
__device__ float g_QP[NCELLS * 256];
__device__ float g_QB[NCELLS * 8];
__device__ float g_QK[NCELLS * 2048];
__device__ float g_WKV[NCELLS * 2048];
__device__ float g_CTX[NCELLS * 256];

// ---------------------------------------------------------------------------
// K1: average-pool per grid cell. grid (32 gi, 256 d, 4 b), 256 threads = h.
// ---------------------------------------------------------------------------
__global__ void k_pool(const float* __restrict__ x) {
    int gi = blockIdx.x, d = blockIdx.y, b = blockIdx.z;
    int t = threadIdx.x;
    const float* p = x + ((size_t)(b * 256 + d) * 256 + (size_t)gi * 8) * 256 + t;
    float s = 0.f;
#pragma unroll
    for (int r = 0; r < 8; r++) s += p[r * 256];
    s += __shfl_down_sync(0xffffffffu, s, 4, 8);
    s += __shfl_down_sync(0xffffffffu, s, 2, 8);
    s += __shfl_down_sync(0xffffffffu, s, 1, 8);
    if ((t & 7) == 0) {
        int j = t >> 3;
        g_Q[((b * 1024 + gi * 32 + j) * 256) + d] = s * (1.0f / 64.0f);
    }
}

// ---------------------------------------------------------------------------
// k2a: QP[4096,256] = Q @ Wq^T + bq.  Tile 64m x 32n, BK=16.
// 256 threads: tm=t&15 (4 m), tn=t>>4 (2 n).
// ---------------------------------------------------------------------------
__global__ void __launch_bounds__(256) k2a(const float* __restrict__ Wq,
                                           const float* __restrict__ bq) {
    __shared__ float As[16 * 68];
    __shared__ float Ws[16 * 36];
    int t = threadIdx.x;
    int m0 = blockIdx.x * 64, n0 = blockIdx.y * 32;
    int tm = t & 15, tn = t >> 4;

    float acc[8];
#pragma unroll
    for (int i = 0; i < 8; i++) acc[i] = 0.f;

    for (int k0 = 0; k0 < 256; k0 += 16) {
        __syncthreads();
        {   // A tile: 64 rows x 16 k
            int r = t >> 2, kq = t & 3;
            float4 v = *(const float4*)&g_Q[(m0 + r) * 256 + k0 + kq * 4];
            As[(kq * 4 + 0) * 68 + r] = v.x;
            As[(kq * 4 + 1) * 68 + r] = v.y;
            As[(kq * 4 + 2) * 68 + r] = v.z;
            As[(kq * 4 + 3) * 68 + r] = v.w;
        }
        if (t < 128) {  // W tile: 32 rows x 16 k
            int n = t >> 2, kq = t & 3;
            float4 v = *(const float4*)&Wq[(n0 + n) * 256 + k0 + kq * 4];
            Ws[(kq * 4 + 0) * 36 + n] = v.x;
            Ws[(kq * 4 + 1) * 36 + n] = v.y;
            Ws[(kq * 4 + 2) * 36 + n] = v.z;
            Ws[(kq * 4 + 3) * 36 + n] = v.w;
        }
        __syncthreads();
#pragma unroll
        for (int k = 0; k < 16; k++) {
            float4 a = *(const float4*)&As[k * 68 + tm * 4];
            float2 bw = *(const float2*)&Ws[k * 36 + tn * 2];
            acc[0] = fmaf(a.x, bw.x, acc[0]); acc[1] = fmaf(a.x, bw.y, acc[1]);
            acc[2] = fmaf(a.y, bw.x, acc[2]); acc[3] = fmaf(a.y, bw.y, acc[3]);
            acc[4] = fmaf(a.z, bw.x, acc[4]); acc[5] = fmaf(a.z, bw.y, acc[5]);
            acc[6] = fmaf(a.w, bw.x, acc[6]); acc[7] = fmaf(a.w, bw.y, acc[7]);
        }
    }
    float b0 = bq[n0 + tn * 2], b1 = bq[n0 + tn * 2 + 1];
#pragma unroll
    for (int i = 0; i < 4; i++) {
        int m = m0 + tm * 4 + i;
        g_QP[m * 256 + n0 + tn * 2 + 0] = acc[i * 2 + 0] + b0;
        g_QP[m * 256 + n0 + tn * 2 + 1] = acc[i * 2 + 1] + b1;
    }
}

// ---------------------------------------------------------------------------
// k_qb: qb[bn][h] = qp_h . bk_h.  grid 128, 256 threads (32 cells x 8 h).
// ---------------------------------------------------------------------------
__global__ void k_qb(const float* __restrict__ bk) {
    int t = threadIdx.x;
    int bn = blockIdx.x * 32 + (t >> 3);
    int h = t & 7;
    float s = 0.f;
#pragma unroll
    for (int j = 0; j < 32; j++)
        s += g_QP[bn * 256 + h * 32 + j] * bk[h * 32 + j];
    g_QB[bn * 8 + h] = s;
}

// ---------------------------------------------------------------------------
// k2b: QK_h[4096,256] = QP_h[4096,32] @ Wk_h[32,256].  Tile 64m x 32n, K=32.
// grid (64 mgrp, 8 ctile, 8 h).
// ---------------------------------------------------------------------------
__global__ void __launch_bounds__(256) k2b(const float* __restrict__ Wk) {
    __shared__ float As[32 * 68];
    __shared__ float Bs[32 * 36];
    int t = threadIdx.x;
    int m0 = blockIdx.x * 64, c0 = blockIdx.y * 32, h = blockIdx.z;
    int tm = t & 15, tn = t >> 4;

    {   // A: 64 rows x 32 k (head slice of QP)
        int r = t >> 2;
#pragma unroll
        for (int q = 0; q < 2; q++) {
            int kq = (t & 3) + q * 4;
            float4 v = *(const float4*)&g_QP[(m0 + r) * 256 + h * 32 + kq * 4];
            As[(kq * 4 + 0) * 68 + r] = v.x;
            As[(kq * 4 + 1) * 68 + r] = v.y;
            As[(kq * 4 + 2) * 68 + r] = v.z;
            As[(kq * 4 + 3) * 68 + r] = v.w;
        }
    }
    {   // B: 32 k-rows x 32 c
        int j = t >> 3, cq = t & 7;
        float4 v = *(const float4*)&Wk[(h * 32 + j) * 256 + c0 + cq * 4];
        *(float4*)&Bs[j * 36 + cq * 4] = v;
    }
    __syncthreads();

    float acc[8];
#pragma unroll
    for (int i = 0; i < 8; i++) acc[i] = 0.f;
#pragma unroll
    for (int k = 0; k < 32; k++) {
        float4 a = *(const float4*)&As[k * 68 + tm * 4];
        float2 bw = *(const float2*)&Bs[k * 36 + tn * 2];
        acc[0] = fmaf(a.x, bw.x, acc[0]); acc[1] = fmaf(a.x, bw.y, acc[1]);
        acc[2] = fmaf(a.y, bw.x, acc[2]); acc[3] = fmaf(a.y, bw.y, acc[3]);
        acc[4] = fmaf(a.z, bw.x, acc[4]); acc[5] = fmaf(a.z, bw.y, acc[5]);
        acc[6] = fmaf(a.w, bw.x, acc[6]); acc[7] = fmaf(a.w, bw.y, acc[7]);
    }
#pragma unroll
    for (int i = 0; i < 4; i++) {
        int m = m0 + tm * 4 + i;
        g_QK[m * 2048 + h * 256 + c0 + tn * 2 + 0] = acc[i * 2 + 0];
        g_QK[m * 2048 + h * 256 + c0 + tn * 2 + 1] = acc[i * 2 + 1];
    }
}

// ---------------------------------------------------------------------------
// k3: per-cell attention. 1 block/cell, 256 threads.
// kvs [d][68] (16B-aligned rows). Phase S: thread (l4,dg) does 4l x 8h x 16d.
// ---------------------------------------------------------------------------
__global__ void __launch_bounds__(256) k3(const float* __restrict__ x) {
    extern __shared__ float sm[];
    float* kvs  = sm;             // 256*68 = 17408
    float* qks  = sm + 17408;     // 8*256  = 2048
    float* psum = sm + 19456;     // 8*8*64 = 4096
    float* as_  = sm + 23552;     // 8*64   = 512
    float* qbs  = sm + 24064;     // 8

    int t = threadIdx.x;
    int bn = blockIdx.x;
    int b = bn >> 10, cell = bn & 1023, gi = cell >> 5, gj = cell & 31;
    const float* xb = x + (size_t)b * 16777216 + (size_t)gi * 2048 + (size_t)gj * 8;

    // load 64x256 patch (32B sectors), store [d][l] at stride 68
#pragma unroll
    for (int i = 0; i < 16; i++) {
        int idx = i * 256 + t;
        int d = idx >> 4, r = idx & 15;
        int sw = r >> 1, part = r & 1;
        float4 v = *(const float4*)(xb + (size_t)d * 65536 + sw * 256 + part * 4);
        int l = sw * 8 + part * 4;
        *(float4*)&kvs[d * 68 + l] = v;
    }
#pragma unroll
    for (int i = 0; i < 8; i++) qks[i * 256 + t] = g_QK[bn * 2048 + i * 256 + t];
    if (t < 8) qbs[t] = g_QB[bn * 8 + t];
    __syncthreads();

    // ---- phase S: score partials ----
    {
        int l4 = t & 15, dg = t >> 4;
        float acc[32];
#pragma unroll
        for (int i = 0; i < 32; i++) acc[i] = 0.f;
#pragma unroll
        for (int dt = 0; dt < 4; dt++) {
            int d0 = dg * 16 + dt * 4;
            float4 kv0 = *(const float4*)&kvs[(d0 + 0) * 68 + l4 * 4];
            float4 kv1 = *(const float4*)&kvs[(d0 + 1) * 68 + l4 * 4];
            float4 kv2 = *(const float4*)&kvs[(d0 + 2) * 68 + l4 * 4];
            float4 kv3 = *(const float4*)&kvs[(d0 + 3) * 68 + l4 * 4];
#pragma unroll
            for (int h = 0; h < 8; h++) {
                float4 qk = *(const float4*)&qks[h * 256 + d0];
                acc[0 * 8 + h] = fmaf(kv0.x, qk.x, acc[0 * 8 + h]);
                acc[1 * 8 + h] = fmaf(kv0.y, qk.x, acc[1 * 8 + h]);
                acc[2 * 8 + h] = fmaf(kv0.z, qk.x, acc[2 * 8 + h]);
                acc[3 * 8 + h] = fmaf(kv0.w, qk.x, acc[3 * 8 + h]);
                acc[0 * 8 + h] = fmaf(kv1.x, qk.y, acc[0 * 8 + h]);
                acc[1 * 8 + h] = fmaf(kv1.y, qk.y, acc[1 * 8 + h]);
                acc[2 * 8 + h] = fmaf(kv1.z, qk.y, acc[2 * 8 + h]);
                acc[3 * 8 + h] = fmaf(kv1.w, qk.y, acc[3 * 8 + h]);
                acc[0 * 8 + h] = fmaf(kv2.x, qk.z, acc[0 * 8 + h]);
                acc[1 * 8 + h] = fmaf(kv2.y, qk.z, acc[1 * 8 + h]);
                acc[2 * 8 + h] = fmaf(kv2.z, qk.z, acc[2 * 8 + h]);
                acc[3 * 8 + h] = fmaf(kv2.w, qk.z, acc[3 * 8 + h]);
                acc[0 * 8 + h] = fmaf(kv3.x, qk.w, acc[0 * 8 + h]);
                acc[1 * 8 + h] = fmaf(kv3.y, qk.w, acc[1 * 8 + h]);
                acc[2 * 8 + h] = fmaf(kv3.z, qk.w, acc[2 * 8 + h]);
                acc[3 * 8 + h] = fmaf(kv3.w, qk.w, acc[3 * 8 + h]);
            }
        }
        // combine dg pairs within warp (lanes differ in bit 4 of t)
#pragma unroll
        for (int i = 0; i < 32; i++)
            acc[i] += __shfl_xor_sync(0xffffffffu, acc[i], 16);
        if ((dg & 1) == 0) {
            int dgp = dg >> 1;
#pragma unroll
            for (int i = 0; i < 4; i++)
#pragma unroll
                for (int h = 0; h < 8; h++)
                    psum[(dgp * 8 + h) * 64 + l4 * 4 + i] = acc[i * 8 + h];
        }
    }
    __syncthreads();

    // ---- softmax: warp h handles head h ----
    {
        int wid = t >> 5, lane = t & 31;
        int h = wid;
        float s1 = qbs[h], s2 = qbs[h];
#pragma unroll
        for (int p = 0; p < 8; p++) {
            s1 += psum[(p * 8 + h) * 64 + lane];
            s2 += psum[(p * 8 + h) * 64 + lane + 32];
        }
        const float sc = 0.17677669529663687f;  // 1/sqrt(32)
        s1 *= sc; s2 *= sc;
        float m = fmaxf(s1, s2);
#pragma unroll
        for (int o = 16; o > 0; o >>= 1) m = fmaxf(m, __shfl_xor_sync(0xffffffffu, m, o));
        float e1 = __expf(s1 - m), e2 = __expf(s2 - m);
        float sum = e1 + e2;
#pragma unroll
        for (int o = 16; o > 0; o >>= 1) sum += __shfl_xor_sync(0xffffffffu, sum, o);
        float inv = 1.f / sum;
        as_[h * 64 + lane]      = e1 * inv;
        as_[h * 64 + lane + 32] = e2 * inv;
    }
    __syncthreads();

    // ---- phase W: wkv[h][d], thread = d ----
    {
        int d = t;
        float acc2[8];
#pragma unroll
        for (int h = 0; h < 8; h++) acc2[h] = 0.f;
#pragma unroll
        for (int l0 = 0; l0 < 64; l0 += 4) {
            float4 kv = *(const float4*)&kvs[d * 68 + l0];
#pragma unroll
            for (int h = 0; h < 8; h++) {
                float4 a4 = *(const float4*)&as_[h * 64 + l0];
                acc2[h] = fmaf(kv.x, a4.x, acc2[h]);
                acc2[h] = fmaf(kv.y, a4.y, acc2[h]);
                acc2[h] = fmaf(kv.z, a4.z, acc2[h]);
                acc2[h] = fmaf(kv.w, a4.w, acc2[h]);
            }
        }
#pragma unroll
        for (int h = 0; h < 8; h++)
            g_WKV[bn * 2048 + h * 256 + d] = acc2[h];
    }
}

// ---------------------------------------------------------------------------
// k4a: CTX_h[4096,32] = WKV_h[4096,256] @ Wv_h^T + bv_h. Tile 64m x 32n, BK=16.
// grid (64 mgrp, 8 h).
// ---------------------------------------------------------------------------
__global__ void __launch_bounds__(256) k4a(const float* __restrict__ Wv,
                                           const float* __restrict__ bv) {
    __shared__ float As[16 * 68];
    __shared__ float Ws[16 * 36];
    int t = threadIdx.x;
    int m0 = blockIdx.x * 64, h = blockIdx.y;
    int tm = t & 15, tn = t >> 4;

    float acc[8];
#pragma unroll
    for (int i = 0; i < 8; i++) acc[i] = 0.f;

    for (int k0 = 0; k0 < 256; k0 += 16) {
        __syncthreads();
        {
            int r = t >> 2, kq = t & 3;
            float4 v = *(const float4*)&g_WKV[(m0 + r) * 2048 + h * 256 + k0 + kq * 4];
            As[(kq * 4 + 0) * 68 + r] = v.x;
            As[(kq * 4 + 1) * 68 + r] = v.y;
            As[(kq * 4 + 2) * 68 + r] = v.z;
            As[(kq * 4 + 3) * 68 + r] = v.w;
        }
        if (t < 128) {
            int n = t >> 2, kq = t & 3;
            float4 v = *(const float4*)&Wv[(h * 32 + n) * 256 + k0 + kq * 4];
            Ws[(kq * 4 + 0) * 36 + n] = v.x;
            Ws[(kq * 4 + 1) * 36 + n] = v.y;
            Ws[(kq * 4 + 2) * 36 + n] = v.z;
            Ws[(kq * 4 + 3) * 36 + n] = v.w;
        }
        __syncthreads();
#pragma unroll
        for (int k = 0; k < 16; k++) {
            float4 a = *(const float4*)&As[k * 68 + tm * 4];
            float2 bw = *(const float2*)&Ws[k * 36 + tn * 2];
            acc[0] = fmaf(a.x, bw.x, acc[0]); acc[1] = fmaf(a.x, bw.y, acc[1]);
            acc[2] = fmaf(a.y, bw.x, acc[2]); acc[3] = fmaf(a.y, bw.y, acc[3]);
            acc[4] = fmaf(a.z, bw.x, acc[4]); acc[5] = fmaf(a.z, bw.y, acc[5]);
            acc[6] = fmaf(a.w, bw.x, acc[6]); acc[7] = fmaf(a.w, bw.y, acc[7]);
        }
    }
    float b0 = bv[h * 32 + tn * 2], b1 = bv[h * 32 + tn * 2 + 1];
#pragma unroll
    for (int i = 0; i < 4; i++) {
        int m = m0 + tm * 4 + i;
        g_CTX[m * 256 + h * 32 + tn * 2 + 0] = acc[i * 2 + 0] + b0;
        g_CTX[m * 256 + h * 32 + tn * 2 + 1] = acc[i * 2 + 1] + b1;
    }
}

// ---------------------------------------------------------------------------
// k4b: OUT = CTX @ Wo^T + bo + Q.  Tile 64m x 32n, BK=16.
// ---------------------------------------------------------------------------
__global__ void __launch_bounds__(256) k4b(const float* __restrict__ Wo,
                                           const float* __restrict__ bo,
                                           float* __restrict__ out) {
    __shared__ float As[16 * 68];
    __shared__ float Ws[16 * 36];
    int t = threadIdx.x;
    int m0 = blockIdx.x * 64, n0 = blockIdx.y * 32;
    int tm = t & 15, tn = t >> 4;

    float acc[8];
#pragma unroll
    for (int i = 0; i < 8; i++) acc[i] = 0.f;

    for (int k0 = 0; k0 < 256; k0 += 16) {
        __syncthreads();
        {
            int r = t >> 2, kq = t & 3;
            float4 v = *(const float4*)&g_CTX[(m0 + r) * 256 + k0 + kq * 4];
            As[(kq * 4 + 0) * 68 + r] = v.x;
            As[(kq * 4 + 1) * 68 + r] = v.y;
            As[(kq * 4 + 2) * 68 + r] = v.z;
            As[(kq * 4 + 3) * 68 + r] = v.w;
        }
        if (t < 128) {
            int n = t >> 2, kq = t & 3;
            float4 v = *(const float4*)&Wo[(n0 + n) * 256 + k0 + kq * 4];
            Ws[(kq * 4 + 0) * 36 + n] = v.x;
            Ws[(kq * 4 + 1) * 36 + n] = v.y;
            Ws[(kq * 4 + 2) * 36 + n] = v.z;
            Ws[(kq * 4 + 3) * 36 + n] = v.w;
        }
        __syncthreads();
#pragma unroll
        for (int k = 0; k < 16; k++) {
            float4 a = *(const float4*)&As[k * 68 + tm * 4];
            float2 bw = *(const float2*)&Ws[k * 36 + tn * 2];
            acc[0] = fmaf(a.x, bw.x, acc[0]); acc[1] = fmaf(a.x, bw.y, acc[1]);
            acc[2] = fmaf(a.y, bw.x, acc[2]); acc[3] = fmaf(a.y, bw.y, acc[3]);
            acc[4] = fmaf(a.z, bw.x, acc[4]); acc[5] = fmaf(a.z, bw.y, acc[5]);
            acc[6] = fmaf(a.w, bw.x, acc[6]); acc[7] = fmaf(a.w, bw.y, acc[7]);
        }
    }
    float b0 = bo[n0 + tn * 2], b1 = bo[n0 + tn * 2 + 1];
#pragma unroll
    for (int i = 0; i < 4; i++) {
        int m = m0 + tm * 4 + i;
        int c = n0 + tn * 2;
        out[m * 256 + c + 0] = acc[i * 2 + 0] + b0 + g_Q[m * 256 + c + 0];
        out[m * 256 + c + 1] = acc[i * 2 + 1] + b1 + g_Q[m * 256 + c + 1];
    }
}

// ---------------------------------------------------------------------------
extern "C" void kernel_launch(void* const* d_in, const int* in_sizes, int n_in,
                              void* d_out, int out_size) {
    const float* x  = (const float*)d_in[0];
    const float* Wq = (const float*)d_in[1];
    const float* bq = (const float*)d_in[2];
    const float* Wk = (const float*)d_in[3];
    const float* bk = (const float*)d_in[4];
    const float* Wv = (const float*)d_in[5];
    const float* bv = (const float*)d_in[6];
    const float* Wo = (const float*)d_in[7];
    const float* bo = (const float*)d_in[8];
    float* out = (float*)d_out;

    const int smem_k3 = 24072 * 4;  // 96,288 B
    cudaFuncSetAttribute(k3, cudaFuncAttributeMaxDynamicSharedMemorySize, smem_k3);

    k_pool<<<dim3(32, 256, 4), 256>>>(x);
    k2a<<<dim3(64, 8), 256>>>(Wq, bq);
    k_qb<<<128, 256>>>(bk);
    k2b<<<dim3(64, 8, 8), 256>>>(Wk);
    k3<<<NCELLS, 256, smem_k3>>>(x);
    k4a<<<dim3(64, 8), 256>>>(Wv, bv);
    k4b<<<dim3(64, 8), 256>>>(Wo, bo, out);
}